// round 2
// baseline (speedup 1.0000x reference)
#include <cuda_runtime.h>
#include <cstdint>

#define NN     16000
#define IN_DIM 128
#define HID    64
#define BB     32
#define PP     128
#define DD     100
#define NCLS   10
#define INV_PI 0.31830988618379067f

// ---------------- scratch (device globals; no allocation allowed) -----------
// Kernels reference these directly (no cudaGetSymbolAddress on the host path).
__device__ float g_filt[NN];                       // node filtration values
__device__ float g_imgs[BB * 2 * DD * DD];         // normalized pers images [B,2,D,D]
__device__ float g_y1[BB * 16 * 50 * 50];          // conv1 pooled out
__device__ float g_y2[BB * 32 * 25 * 25];          // conv2 pooled out

// ======================= K1: node filtration MLP ============================
// h = relu(x@w1 + b1); filt = sigmoid(h@w2 + b2)
// Block: 256 threads = 4 groups of 64 (one node per group, thread j = hidden j)
__global__ __launch_bounds__(256) void filt_kernel(
    const float* __restrict__ x, const float* __restrict__ w1,
    const float* __restrict__ b1, const float* __restrict__ w2,
    const float* __restrict__ b2, float* __restrict__ out_filt)
{
    __shared__ float w1s[IN_DIM * HID];   // 32 KB
    __shared__ float b1s[HID], w2s[HID];
    __shared__ float xs[4][IN_DIM];
    __shared__ float red[4][2];

    const int tid = threadIdx.x;
    for (int i = tid; i < IN_DIM * HID; i += 256) w1s[i] = w1[i];
    if (tid < HID) { b1s[tid] = b1[tid]; w2s[tid] = w2[tid]; }
    const float b2v = b2[0];

    const int g = tid >> 6;        // group 0..3
    const int j = tid & 63;        // hidden unit

    for (int base = blockIdx.x * 4; base < NN; base += gridDim.x * 4) {
        const int node = base + g;
        __syncthreads();           // protects xs/red reuse + first-iter w1s
        if (node < NN) {
            xs[g][j]      = x[node * IN_DIM + j];
            xs[g][j + 64] = x[node * IN_DIM + 64 + j];
        }
        __syncthreads();
        if (node < NN) {
            float s = b1s[j];
            #pragma unroll 8
            for (int i = 0; i < IN_DIM; ++i)
                s += xs[g][i] * w1s[i * HID + j];
            float v = fmaxf(s, 0.f) * w2s[j];
            #pragma unroll
            for (int off = 16; off; off >>= 1)
                v += __shfl_down_sync(0xffffffffu, v, off);
            if ((tid & 31) == 0) red[g][(tid >> 5) & 1] = v;
        }
        __syncthreads();
        if (node < NN && j == 0) {
            float t = red[g][0] + red[g][1] + b2v;
            float f = 1.f / (1.f + __expf(-t));
            g_filt[node]   = f;
            out_filt[node] = f;
        }
    }
}

// ================ K2: persistence image (gather + exp + GEMM + norm) ========
// One block per image m in [0,64): b = m>>1, ch = m&1.
// 2*VAR = 1.0, so the Gaussian factorizes:
//   im[i,j] = sum_p U[p,i] * V[p,j],
//   U[p,i] = exp(-(birth_p - i/D)^2),  V[p,j] = exp(-(pers_p - j/D)^2)/pi
// then im /= max(im).  U,V live entirely in smem; 4x4 register tiles.
#define PERS_SMEM_FLOATS (2 * PP * DD + PP + PP + 32)
__global__ __launch_bounds__(256) void pers_image_kernel(
    const int* __restrict__ pidx0, const int* __restrict__ pidx1)
{
    extern __shared__ float sm[];
    float* Us = sm;                 // [128][100]
    float* Vs = Us + PP * DD;       // [128][100]
    float* bs = Vs + PP * DD;       // births [128]
    float* ps = bs + PP;            // persistence [128]
    float* red = ps + PP;           // [32]

    const int m  = blockIdx.x;
    const int b  = m >> 1;
    const int ch = m & 1;
    const int* pidx = ch ? pidx1 : pidx0;
    const int tid = threadIdx.x;

    if (tid < PP) {
        int i0 = pidx[(b * PP + tid) * 2 + 0];
        int i1 = pidx[(b * PP + tid) * 2 + 1];
        float birth = g_filt[i0];
        bs[tid] = birth;
        ps[tid] = g_filt[i1] - birth;
    }
    __syncthreads();

    for (int idx = tid; idx < PP * DD; idx += 256) {
        int p = idx / DD, t = idx % DD;
        float c  = (float)t * 0.01f;
        float db = bs[p] - c;
        float dp = ps[p] - c;
        Us[idx] = __expf(-db * db);
        Vs[idx] = INV_PI * __expf(-dp * dp);
    }
    __syncthreads();

    // 625 tiles of 4x4 outputs; up to 3 tiles per thread
    float tv[48];
    float mx = 0.f;
    #pragma unroll
    for (int it = 0; it < 3; ++it) {
        const int tile = tid + it * 256;
        if (tile < 625) {
            const int i0 = (tile / 25) * 4;
            const int j0 = (tile % 25) * 4;
            float acc[16];
            #pragma unroll
            for (int k = 0; k < 16; ++k) acc[k] = 0.f;
            #pragma unroll 4
            for (int p = 0; p < PP; ++p) {
                float4 u = *reinterpret_cast<const float4*>(Us + p * DD + i0);
                float4 v = *reinterpret_cast<const float4*>(Vs + p * DD + j0);
                acc[0]  += u.x * v.x; acc[1]  += u.x * v.y; acc[2]  += u.x * v.z; acc[3]  += u.x * v.w;
                acc[4]  += u.y * v.x; acc[5]  += u.y * v.y; acc[6]  += u.y * v.z; acc[7]  += u.y * v.w;
                acc[8]  += u.z * v.x; acc[9]  += u.z * v.y; acc[10] += u.z * v.z; acc[11] += u.z * v.w;
                acc[12] += u.w * v.x; acc[13] += u.w * v.y; acc[14] += u.w * v.z; acc[15] += u.w * v.w;
            }
            #pragma unroll
            for (int k = 0; k < 16; ++k) {
                tv[it * 16 + k] = acc[k];
                mx = fmaxf(mx, acc[k]);
            }
        }
    }
    // block max reduction
    #pragma unroll
    for (int off = 16; off; off >>= 1)
        mx = fmaxf(mx, __shfl_down_sync(0xffffffffu, mx, off));
    if ((tid & 31) == 0) red[tid >> 5] = mx;
    __syncthreads();
    if (tid == 0) {
        float t = red[0];
        #pragma unroll
        for (int w = 1; w < 8; ++w) t = fmaxf(t, red[w]);
        red[0] = t;
    }
    __syncthreads();
    const float inv = 1.f / red[0];

    float* outp = g_imgs + m * (DD * DD);
    #pragma unroll
    for (int it = 0; it < 3; ++it) {
        const int tile = tid + it * 256;
        if (tile < 625) {
            const int i0 = (tile / 25) * 4;
            const int j0 = (tile % 25) * 4;
            #pragma unroll
            for (int a = 0; a < 4; ++a)
                #pragma unroll
                for (int c = 0; c < 4; ++c)
                    outp[(i0 + a) * DD + (j0 + c)] = tv[it * 16 + a * 4 + c] * inv;
        }
    }
}

// ============= K3/K4: fused conv(5x5, pad2) + ReLU + maxpool(2x2) ===========
// Template on input channels IC, spatial W, channels per block OC_BLOCK,
// pooled rows per block PR, output channels per thread OPT.
// Each thread computes a 2x2 conv quad (one pooled output) for OPT channels,
// loading the shared 6x6 input patch once per input channel.
template<int IC, int W, int OC_BLOCK, int PR, int OPT>
__global__ __launch_bounds__(256) void conv_pool_kernel(
    const float* __restrict__ in, const float* __restrict__ wts,
    const float* __restrict__ bias, float* __restrict__ out, int total_oc)
{
    constexpr int TR = 2 * PR + 4;   // tile rows incl. halo
    constexpr int WP = W + 4;        // padded width
    constexpr int PC = W / 2;        // pooled cols
    extern __shared__ float smc[];
    float* tile = smc;                       // IC*TR*WP
    float* wsm  = tile + IC * TR * WP;       // OC_BLOCK*IC*25
    float* bsm  = wsm + OC_BLOCK * IC * 25;  // OC_BLOCK

    const int img = blockIdx.x, rg = blockIdx.y, ocg = blockIdx.z;
    const int prStart = rg * PR;
    const int ocStart = ocg * OC_BLOCK;
    const int tid = threadIdx.x;

    for (int idx = tid; idx < OC_BLOCK * IC * 25; idx += 256)
        wsm[idx] = wts[ocStart * IC * 25 + idx];
    if (tid < OC_BLOCK) bsm[tid] = bias[ocStart + tid];

    const int y0 = prStart * 2 - 2;
    for (int idx = tid; idx < IC * TR * WP; idx += 256) {
        const int ic = idx / (TR * WP);
        const int r  = (idx / WP) % TR;
        const int c  = idx % WP;
        const int y = y0 + r, xx = c - 2;
        float v = 0.f;
        if (y >= 0 && y < W && xx >= 0 && xx < W)
            v = in[((img * IC + ic) * W + y) * W + xx];
        tile[idx] = v;
    }
    __syncthreads();

    constexpr int NOCQ = OC_BLOCK / OPT;
    const int nPos = PR * PC * NOCQ;
    for (int pos = tid; pos < nPos; pos += 256) {
        const int sp  = pos % (PR * PC);
        const int ocq = pos / (PR * PC);
        const int pr = sp / PC, pc = sp % PC;
        float acc[OPT][4];
        #pragma unroll
        for (int o = 0; o < OPT; ++o)
            acc[o][0] = acc[o][1] = acc[o][2] = acc[o][3] = 0.f;
        const int ty = 2 * pr, tx = 2 * pc;

        for (int ic = 0; ic < IC; ++ic) {
            float patch[6][6];
            const float* tptr = tile + (ic * TR + ty) * WP + tx;
            #pragma unroll
            for (int r = 0; r < 6; ++r)
                #pragma unroll
                for (int c = 0; c < 6; ++c)
                    patch[r][c] = tptr[r * WP + c];
            #pragma unroll
            for (int o = 0; o < OPT; ++o) {
                const float* wp = wsm + ((ocq * OPT + o) * IC + ic) * 25;
                #pragma unroll
                for (int ky = 0; ky < 5; ++ky)
                    #pragma unroll
                    for (int kx = 0; kx < 5; ++kx) {
                        const float wv = wp[ky * 5 + kx];
                        acc[o][0] += patch[ky][kx]         * wv;
                        acc[o][1] += patch[ky][kx + 1]     * wv;
                        acc[o][2] += patch[ky + 1][kx]     * wv;
                        acc[o][3] += patch[ky + 1][kx + 1] * wv;
                    }
            }
        }
        #pragma unroll
        for (int o = 0; o < OPT; ++o) {
            const int oc = ocStart + ocq * OPT + o;
            float mv = fmaxf(fmaxf(acc[o][0], acc[o][1]),
                             fmaxf(acc[o][2], acc[o][3])) + bsm[ocq * OPT + o];
            mv = fmaxf(mv, 0.f);
            out[((img * total_oc + oc) * PC + (prStart + pr)) * PC + pc] = mv;
        }
    }
}

// ======================= K5: FC head ========================================
__global__ __launch_bounds__(256) void fc_kernel(
    const float* __restrict__ w, const float* __restrict__ b,
    float* __restrict__ out)
{
    const int bc = blockIdx.x;
    const int bi = bc / NCLS, c = bc % NCLS;
    const float4* yb = reinterpret_cast<const float4*>(g_y2 + bi * 20000);
    const float4* wc = reinterpret_cast<const float4*>(w + c * 20000);
    float s = 0.f;
    for (int k = threadIdx.x; k < 5000; k += 256) {
        float4 a = yb[k], ww = wc[k];
        s += a.x * ww.x + a.y * ww.y + a.z * ww.z + a.w * ww.w;
    }
    #pragma unroll
    for (int off = 16; off; off >>= 1)
        s += __shfl_down_sync(0xffffffffu, s, off);
    __shared__ float red[8];
    if ((threadIdx.x & 31) == 0) red[threadIdx.x >> 5] = s;
    __syncthreads();
    if (threadIdx.x == 0) {
        float t = 0.f;
        #pragma unroll
        for (int wi = 0; wi < 8; ++wi) t += red[wi];
        out[bi * NCLS + c] = t + b[c];
    }
}

// ============================== launch ======================================
extern "C" void kernel_launch(void* const* d_in, const int* in_sizes, int n_in,
                              void* d_out, int out_size)
{
    const float* x        = (const float*)d_in[0];
    const int*   pidx0    = (const int*)  d_in[1];
    const int*   pidx1    = (const int*)  d_in[2];
    const float* w1       = (const float*)d_in[3];
    const float* b1       = (const float*)d_in[4];
    const float* w2       = (const float*)d_in[5];
    const float* b2       = (const float*)d_in[6];
    const float* conv1_w  = (const float*)d_in[7];
    const float* conv1_b  = (const float*)d_in[8];
    const float* conv2_w  = (const float*)d_in[9];
    const float* conv2_b  = (const float*)d_in[10];
    const float* out_w    = (const float*)d_in[11];
    const float* out_b    = (const float*)d_in[12];
    float* out = (float*)d_out;

    // device scratch addresses (resolved at load, not per-call):
    float* imgs; float* y1; float* y2;
    // direct device-symbol references inside kernels; only conv/pers need ptrs
    static float* s_imgs = nullptr; static float* s_y1 = nullptr; static float* s_y2 = nullptr;
    if (!s_imgs) {   // one-time, deterministic address lookups (not stream ops)
        cudaGetSymbolAddress((void**)&s_imgs, g_imgs);
        cudaGetSymbolAddress((void**)&s_y1,   g_y1);
        cudaGetSymbolAddress((void**)&s_y2,   g_y2);
        cudaFuncSetAttribute(pers_image_kernel,
            cudaFuncAttributeMaxDynamicSharedMemorySize, PERS_SMEM_FLOATS * 4);
        cudaFuncSetAttribute((const void*)conv_pool_kernel<16, 50, 16, 5, 4>,
            cudaFuncAttributeMaxDynamicSharedMemorySize,
            (16 * 14 * 54 + 16 * 16 * 25 + 16) * 4);
    }
    imgs = s_imgs; y1 = s_y1; y2 = s_y2;

    const int pers_smem  = PERS_SMEM_FLOATS * 4;                        // 103552
    const int conv1_smem = (2 * 24 * 104 + 16 * 2 * 25 + 16) * 4;      // 23232
    const int conv2_smem = (16 * 14 * 54 + 16 * 16 * 25 + 16) * 4;     // 74048

    // K1: node filtration -> g_filt and d_out[320:]
    filt_kernel<<<250, 256>>>(x, w1, b1, w2, b2, out + BB * NCLS);

    // K2: persistence images -> g_imgs [B,2,100,100]
    pers_image_kernel<<<64, 256, pers_smem>>>(pidx0, pidx1);

    // K3: conv1 + relu + pool  [B,2,100,100] -> [B,16,50,50]
    conv_pool_kernel<2, 100, 16, 10, 4><<<dim3(32, 5, 1), 256, conv1_smem>>>(
        imgs, conv1_w, conv1_b, y1, 16);

    // K4: conv2 + relu + pool  [B,16,50,50] -> [B,32,25,25]
    conv_pool_kernel<16, 50, 16, 5, 4><<<dim3(32, 5, 2), 256, conv2_smem>>>(
        y1, conv2_w, conv2_b, y2, 32);

    // K5: FC -> d_out[0:320]
    fc_kernel<<<BB * NCLS, 256>>>(out_w, out_b, out);
}

// round 4
// speedup vs baseline: 1.2623x; 1.2623x over previous
#include <cuda_runtime.h>
#include <cstdint>

#define NN     16000
#define IN_DIM 128
#define HID    64
#define BB     32
#define PP     128
#define DD     100
#define NCLS   10
#define INV_PI 0.31830988618379067f

// ---------------- scratch (device globals; no allocation allowed) -----------
__device__ float g_filt[NN];                       // node filtration values
__device__ float g_imgs[BB * 2 * DD * DD];         // normalized pers images [B,2,D,D]
__device__ float g_y1[BB * 16 * 50 * 50];          // conv1 pooled out
__device__ float g_y2[BB * 32 * 25 * 25];          // conv2 pooled out

// ======================= K1: node filtration MLP ============================
// h = relu(x@w1+b1); filt = sigmoid(h@w2+b2).
// 256 threads: thread = (chunk = tid>>6 in [0,4), j = tid&63).
// w1 column-slice held in registers (32 per thread); x via float4 broadcast.
__global__ __launch_bounds__(256) void filt_kernel(
    const float* __restrict__ x, const float* __restrict__ w1,
    const float* __restrict__ b1, const float* __restrict__ w2,
    const float* __restrict__ b2, float* __restrict__ out_filt)
{
    const int tid   = threadIdx.x;
    const int j     = tid & 63;
    const int chunk = tid >> 6;

    float wr[32];
    #pragma unroll
    for (int k = 0; k < 32; ++k)
        wr[k] = w1[(chunk * 32 + k) * HID + j];
    const float b1j = b1[j];
    const float w2j = w2[j];
    const float b2v = b2[0];

    __shared__ float xs[4][IN_DIM];      // 4 nodes of input
    __shared__ float part[4][4 * 64];    // [node][chunk*64 + j]
    __shared__ float nsum[4][2];

    // 250 blocks x 64 nodes = 16000 exactly; 16 groups of 4 nodes per block
    for (int grp = 0; grp < 16; ++grp) {
        const int nbase = blockIdx.x * 64 + grp * 4;
        __syncthreads();   // protect xs/part/nsum reuse
        for (int idx = tid; idx < 4 * IN_DIM; idx += 256) {
            int n = idx >> 7, c = idx & 127;
            xs[n][c] = x[(nbase + n) * IN_DIM + c];
        }
        __syncthreads();

        #pragma unroll
        for (int n = 0; n < 4; ++n) {
            const float4* xp = reinterpret_cast<const float4*>(xs[n] + chunk * 32);
            float s = 0.f;
            #pragma unroll
            for (int q = 0; q < 8; ++q) {
                float4 v = xp[q];
                s += v.x * wr[4 * q] + v.y * wr[4 * q + 1]
                   + v.z * wr[4 * q + 2] + v.w * wr[4 * q + 3];
            }
            part[n][chunk * 64 + j] = s;
        }
        __syncthreads();

        // reduce: thread -> (node = tid>>6, this thread's j)
        {
            const int n2 = chunk;
            float v = part[n2][j] + part[n2][64 + j]
                    + part[n2][128 + j] + part[n2][192 + j] + b1j;
            float h = fmaxf(v, 0.f) * w2j;
            #pragma unroll
            for (int off = 16; off; off >>= 1)
                h += __shfl_down_sync(0xffffffffu, h, off);
            if ((j & 31) == 0) nsum[n2][j >> 5] = h;
        }
        __syncthreads();
        if (tid < 4) {
            const int node = nbase + tid;
            float t = nsum[tid][0] + nsum[tid][1] + b2v;
            float f = 1.f / (1.f + __expf(-t));
            g_filt[node]   = f;
            out_filt[node] = f;
        }
    }
}

// ================ K2: persistence image (gather + exp + GEMM + norm) ========
// 2*VAR = 1.0 -> Gaussian factorizes: im = U^T V (K=128), then /= max.
#define PERS_SMEM_FLOATS (2 * PP * DD + PP + PP + 32)
__global__ __launch_bounds__(256) void pers_image_kernel(
    const int* __restrict__ pidx0, const int* __restrict__ pidx1)
{
    extern __shared__ float sm[];
    float* Us = sm;                 // [128][100]
    float* Vs = Us + PP * DD;       // [128][100]
    float* bs = Vs + PP * DD;
    float* ps = bs + PP;
    float* red = ps + PP;

    const int m  = blockIdx.x;
    const int b  = m >> 1;
    const int ch = m & 1;
    const int* pidx = ch ? pidx1 : pidx0;
    const int tid = threadIdx.x;

    if (tid < PP) {
        int i0 = pidx[(b * PP + tid) * 2 + 0];
        int i1 = pidx[(b * PP + tid) * 2 + 1];
        float birth = g_filt[i0];
        bs[tid] = birth;
        ps[tid] = g_filt[i1] - birth;
    }
    __syncthreads();

    for (int idx = tid; idx < PP * DD; idx += 256) {
        int p = idx / DD, t = idx % DD;
        float c  = (float)t * 0.01f;
        float db = bs[p] - c;
        float dp = ps[p] - c;
        Us[idx] = __expf(-db * db);
        Vs[idx] = INV_PI * __expf(-dp * dp);
    }
    __syncthreads();

    float tv[48];
    float mx = 0.f;
    #pragma unroll
    for (int it = 0; it < 3; ++it) {
        const int tile = tid + it * 256;
        if (tile < 625) {
            const int i0 = (tile / 25) * 4;
            const int j0 = (tile % 25) * 4;
            float acc[16];
            #pragma unroll
            for (int k = 0; k < 16; ++k) acc[k] = 0.f;
            #pragma unroll 4
            for (int p = 0; p < PP; ++p) {
                float4 u = *reinterpret_cast<const float4*>(Us + p * DD + i0);
                float4 v = *reinterpret_cast<const float4*>(Vs + p * DD + j0);
                acc[0]  += u.x * v.x; acc[1]  += u.x * v.y; acc[2]  += u.x * v.z; acc[3]  += u.x * v.w;
                acc[4]  += u.y * v.x; acc[5]  += u.y * v.y; acc[6]  += u.y * v.z; acc[7]  += u.y * v.w;
                acc[8]  += u.z * v.x; acc[9]  += u.z * v.y; acc[10] += u.z * v.z; acc[11] += u.z * v.w;
                acc[12] += u.w * v.x; acc[13] += u.w * v.y; acc[14] += u.w * v.z; acc[15] += u.w * v.w;
            }
            #pragma unroll
            for (int k = 0; k < 16; ++k) {
                tv[it * 16 + k] = acc[k];
                mx = fmaxf(mx, acc[k]);
            }
        }
    }
    #pragma unroll
    for (int off = 16; off; off >>= 1)
        mx = fmaxf(mx, __shfl_down_sync(0xffffffffu, mx, off));
    if ((tid & 31) == 0) red[tid >> 5] = mx;
    __syncthreads();
    if (tid == 0) {
        float t = red[0];
        #pragma unroll
        for (int w = 1; w < 8; ++w) t = fmaxf(t, red[w]);
        red[0] = t;
    }
    __syncthreads();
    const float inv = 1.f / red[0];

    float* outp = g_imgs + m * (DD * DD);
    #pragma unroll
    for (int it = 0; it < 3; ++it) {
        const int tile = tid + it * 256;
        if (tile < 625) {
            const int i0 = (tile / 25) * 4;
            const int j0 = (tile % 25) * 4;
            #pragma unroll
            for (int a = 0; a < 4; ++a)
                #pragma unroll
                for (int c = 0; c < 4; ++c)
                    outp[(i0 + a) * DD + (j0 + c)] = tv[it * 16 + a * 4 + c] * inv;
        }
    }
}

// ============= K3/K4: fused conv(5x5, pad2) + ReLU + maxpool(2x2) ===========
// OPT=4 output channels per thread, one pooled (2x2 conv) quad per thread.
// Weights padded to 28 floats -> 7 broadcast LDS.128 per (oc,ic).
// Patch rows loaded as float2 (lane stride 8B -> conflict-free 2-cyc waves).
// SEL picks src/dst device globals: 0 = imgs->y1, 1 = y1->y2.
template<int IC, int W, int OC_BLOCK, int PR, int SEL>
__global__ __launch_bounds__(224, 2) void conv_pool_kernel(
    const float* __restrict__ wts, const float* __restrict__ bias)
{
    constexpr int OPT = 4;
    constexpr int TR  = 2 * PR + 4;   // tile rows incl. halo
    constexpr int WP  = W + 4;        // padded width
    constexpr int PC  = W / 2;        // pooled cols (= pooled rows)
    constexpr int NOCQ = OC_BLOCK / OPT;
    const float* in  = (SEL == 0) ? g_imgs : g_y1;
    float*       out = (SEL == 0) ? g_y1   : g_y2;
    const int total_oc = (SEL == 0) ? 16 : 32;

    extern __shared__ float smc[];
    float* tile = smc;                        // IC*TR*WP
    float* wsm  = tile + IC * TR * WP;        // OC_BLOCK*IC*28  (16B aligned)
    float* bsm  = wsm + OC_BLOCK * IC * 28;   // OC_BLOCK

    const int img = blockIdx.x, rg = blockIdx.y, ocg = blockIdx.z;
    const int prStart = rg * PR;
    const int ocStart = ocg * OC_BLOCK;
    const int tid = threadIdx.x;

    for (int idx = tid; idx < OC_BLOCK * IC * 28; idx += blockDim.x) {
        const int oc = idx / (IC * 28);
        const int r  = idx % (IC * 28);
        const int ic = r / 28, k = r % 28;
        wsm[idx] = (k < 25) ? wts[((ocStart + oc) * IC + ic) * 25 + k] : 0.f;
    }
    if (tid < OC_BLOCK) bsm[tid] = bias[ocStart + tid];

    const int y0 = prStart * 2 - 2;
    for (int idx = tid; idx < IC * TR * WP; idx += blockDim.x) {
        const int ic = idx / (TR * WP);
        const int r  = (idx / WP) % TR;
        const int c  = idx % WP;
        const int y = y0 + r, xx = c - 2;
        float v = 0.f;
        if (y >= 0 && y < W && xx >= 0 && xx < W)
            v = in[((img * IC + ic) * W + y) * W + xx];
        tile[idx] = v;
    }
    __syncthreads();

    const int nPos = PR * PC * NOCQ;
    for (int pos = tid; pos < nPos; pos += blockDim.x) {
        const int sp  = pos % (PR * PC);
        const int ocq = pos / (PR * PC);
        const int pr = sp / PC, pc = sp % PC;
        if (prStart + pr >= PC) continue;      // conv2: 25 rows, grid covers 26
        const int ty = 2 * pr, tx = 2 * pc;

        float acc[OPT][4];
        #pragma unroll
        for (int o = 0; o < OPT; ++o)
            acc[o][0] = acc[o][1] = acc[o][2] = acc[o][3] = 0.f;

        #pragma unroll 1
        for (int ic = 0; ic < IC; ++ic) {
            float patch[6][6];
            const float* tp = tile + (ic * TR + ty) * WP + tx;
            #pragma unroll
            for (int r = 0; r < 6; ++r) {
                float2 a = *reinterpret_cast<const float2*>(tp + r * WP);
                float2 bq = *reinterpret_cast<const float2*>(tp + r * WP + 2);
                float2 c = *reinterpret_cast<const float2*>(tp + r * WP + 4);
                patch[r][0] = a.x;  patch[r][1] = a.y;
                patch[r][2] = bq.x; patch[r][3] = bq.y;
                patch[r][4] = c.x;  patch[r][5] = c.y;
            }
            #pragma unroll
            for (int o = 0; o < OPT; ++o) {
                const float4* w4 = reinterpret_cast<const float4*>(
                    wsm + ((ocq * OPT + o) * IC + ic) * 28);
                float wv[28];
                #pragma unroll
                for (int q = 0; q < 7; ++q)
                    *reinterpret_cast<float4*>(wv + 4 * q) = w4[q];
                #pragma unroll
                for (int ky = 0; ky < 5; ++ky)
                    #pragma unroll
                    for (int kx = 0; kx < 5; ++kx) {
                        const float wgt = wv[ky * 5 + kx];
                        acc[o][0] += patch[ky][kx]         * wgt;
                        acc[o][1] += patch[ky][kx + 1]     * wgt;
                        acc[o][2] += patch[ky + 1][kx]     * wgt;
                        acc[o][3] += patch[ky + 1][kx + 1] * wgt;
                    }
            }
        }
        #pragma unroll
        for (int o = 0; o < OPT; ++o) {
            const int oc = ocStart + ocq * OPT + o;
            float mv = fmaxf(fmaxf(acc[o][0], acc[o][1]),
                             fmaxf(acc[o][2], acc[o][3])) + bsm[ocq * OPT + o];
            mv = fmaxf(mv, 0.f);
            out[((img * total_oc + oc) * PC + (prStart + pr)) * PC + pc] = mv;
        }
    }
}

// ======================= K5: FC head ========================================
__global__ __launch_bounds__(256) void fc_kernel(
    const float* __restrict__ w, const float* __restrict__ b,
    float* __restrict__ out)
{
    const int bc = blockIdx.x;
    const int bi = bc / NCLS, c = bc % NCLS;
    const float4* yb = reinterpret_cast<const float4*>(g_y2 + bi * 20000);
    const float4* wc = reinterpret_cast<const float4*>(w + c * 20000);
    float s = 0.f;
    for (int k = threadIdx.x; k < 5000; k += 256) {
        float4 a = yb[k], ww = wc[k];
        s += a.x * ww.x + a.y * ww.y + a.z * ww.z + a.w * ww.w;
    }
    #pragma unroll
    for (int off = 16; off; off >>= 1)
        s += __shfl_down_sync(0xffffffffu, s, off);
    __shared__ float red[8];
    if ((threadIdx.x & 31) == 0) red[threadIdx.x >> 5] = s;
    __syncthreads();
    if (threadIdx.x == 0) {
        float t = 0.f;
        #pragma unroll
        for (int wi = 0; wi < 8; ++wi) t += red[wi];
        out[bi * NCLS + c] = t + b[c];
    }
}

// ============================== launch ======================================
extern "C" void kernel_launch(void* const* d_in, const int* in_sizes, int n_in,
                              void* d_out, int out_size)
{
    const float* x        = (const float*)d_in[0];
    const int*   pidx0    = (const int*)  d_in[1];
    const int*   pidx1    = (const int*)  d_in[2];
    const float* w1       = (const float*)d_in[3];
    const float* b1       = (const float*)d_in[4];
    const float* w2       = (const float*)d_in[5];
    const float* b2       = (const float*)d_in[6];
    const float* conv1_w  = (const float*)d_in[7];
    const float* conv1_b  = (const float*)d_in[8];
    const float* conv2_w  = (const float*)d_in[9];
    const float* conv2_b  = (const float*)d_in[10];
    const float* out_w    = (const float*)d_in[11];
    const float* out_b    = (const float*)d_in[12];
    float* out = (float*)d_out;

    const int pers_smem  = PERS_SMEM_FLOATS * 4;                      // 103552
    const int conv1_smem = (2 * 8 * 104 + 16 * 2 * 28 + 16) * 4;     // 10304
    const int conv2_smem = (16 * 8 * 54 + 16 * 16 * 28 + 16) * 4;    // 56384

    cudaFuncSetAttribute(pers_image_kernel,
        cudaFuncAttributeMaxDynamicSharedMemorySize, pers_smem);
    cudaFuncSetAttribute((const void*)conv_pool_kernel<16, 50, 16, 2, 1>,
        cudaFuncAttributeMaxDynamicSharedMemorySize, conv2_smem);

    // K1: node filtration -> g_filt and d_out[320:]
    filt_kernel<<<250, 256>>>(x, w1, b1, w2, b2, out + BB * NCLS);

    // K2: persistence images -> g_imgs [B,2,100,100]
    pers_image_kernel<<<64, 256, pers_smem>>>(pidx0, pidx1);

    // K3: conv1 + relu + pool  [B,2,100,100] -> [B,16,50,50]
    conv_pool_kernel<2, 100, 16, 2, 0><<<dim3(32, 25, 1), 224, conv1_smem>>>(
        conv1_w, conv1_b);

    // K4: conv2 + relu + pool  [B,16,50,50] -> [B,32,25,25]
    conv_pool_kernel<16, 50, 16, 2, 1><<<dim3(32, 13, 2), 224, conv2_smem>>>(
        conv2_w, conv2_b);

    // K5: FC -> d_out[0:320]
    fc_kernel<<<BB * NCLS, 256>>>(out_w, out_b, out);
}